// round 8
// baseline (speedup 1.0000x reference)
#include <cuda_runtime.h>
#include <cuda_bf16.h>
#include <cstdint>

// Problem constants
#define NB 4
#define NC 64
#define NHH 256
#define NWW 256
#define NH 63
#define NW 63
#define LPB (NH*NW)        // 3969
#define M_TOT (NB*LPB)     // 15876
#define M_PAD 16000
#define KDIM 4096
#define HID 256
#define TOT ((size_t)NB*NC*NHH*NWW)   // 16777216

// FP8 scaling: W1 stored *16 (descale 1/16), W2 stored *1024 (descale 1/1024)
#define SC1 0.0625f
#define SC2 0.0009765625f

// Scratch (static device globals)
static __device__ uint8_t g_x8[(size_t)TOT];                 // 16.7 MB  x in e4m3
static __device__ uint8_t g_W18[(size_t)HID*KDIM];           // 1 MB     16*W1 e4m3
static __device__ uint8_t g_W28[(size_t)KDIM*HID];           // 1 MB     1024*W2 e4m3
static __device__ uint8_t g_G8[(size_t)M_PAD*HID];           // 4 MB     GELU(h) e4m3
static __device__ __nv_bfloat16 g_img[(size_t)4*TOT];        // 134 MB   4 phase images
static __device__ float g_alpha;

// ---------------------------------------------------------------------------
// helpers
// ---------------------------------------------------------------------------
__device__ __forceinline__ void ldm4(uint32_t& r0, uint32_t& r1, uint32_t& r2, uint32_t& r3, uint32_t a){
  asm volatile("ldmatrix.sync.aligned.m8n8.x4.shared.b16 {%0,%1,%2,%3},[%4];\n"
    : "=r"(r0), "=r"(r1), "=r"(r2), "=r"(r3) : "r"(a));
}
__device__ __forceinline__ void mma_fp8(float* d, const uint32_t* a, const uint32_t* b){
  asm volatile("mma.sync.aligned.m16n8k32.row.col.f32.e4m3.e4m3.f32 "
    "{%0,%1,%2,%3},{%4,%5,%6,%7},{%8,%9},{%0,%1,%2,%3};\n"
    : "+f"(d[0]), "+f"(d[1]), "+f"(d[2]), "+f"(d[3])
    : "r"(a[0]), "r"(a[1]), "r"(a[2]), "r"(a[3]), "r"(b[0]), "r"(b[1]));
}
// pack 2/4 floats to e4m3 (first arg -> lowest byte)
__device__ __forceinline__ unsigned short fp8x2(float v0, float v1){
  unsigned short p;
  asm("cvt.rn.satfinite.e4m3x2.f32 %0, %1, %2;" : "=h"(p) : "f"(v1), "f"(v0));
  return p;
}
__device__ __forceinline__ uint32_t fp8x4(float a, float b, float c, float d){
  unsigned short lo = fp8x2(a, b), hi = fp8x2(c, d);
  return (uint32_t)lo | ((uint32_t)hi << 16);
}

// smem tile: rows x 4 chunks of 16B (BK = 64 fp8). XOR swizzle, conflict-free ldmatrix.
__device__ __forceinline__ int sw_idx(int row, int ch){ return row*4 + (ch ^ ((row>>1)&3)); }

// One BK=64 slab per warp: 2 k32 steps; warp tile 32(M) x 64(N).
// Block: BM=64 (wm in {0,1}), BN=256 (wn in {0..3}).
__device__ __forceinline__ void compute_tile(const uint4* sA, const uint4* sB,
                                             int wm, int wn, int lane, float (*acc)[8][4]){
  uint32_t baseA = (uint32_t)__cvta_generic_to_shared(sA);
  uint32_t baseB = (uint32_t)__cvta_generic_to_shared(sB);
  const int g = lane >> 3, l7 = lane & 7;
  #pragma unroll
  for (int ks = 0; ks < 2; ks++){
    uint32_t afr[2][4], bfr[8][2];
    // A fragments: a0=rows r..r+7 ch0, a1=rows+8 ch0, a2=rows ch1, a3=rows+8 ch1
    #pragma unroll
    for (int mt = 0; mt < 2; mt++){
      int row = wm*32 + mt*16 + (g & 1)*8 + l7;
      int ch  = 2*ks + (g >> 1);
      ldm4(afr[mt][0], afr[mt][1], afr[mt][2], afr[mt][3], baseA + (sw_idx(row, ch) << 4));
    }
    // B fragments: mat0=n..n+7 ch0 (b0 t0), mat1=n..n+7 ch1 (b1 t0), mat2/3 = n+8 tile
    #pragma unroll
    for (int ntp = 0; ntp < 4; ntp++){
      int row = wn*64 + ntp*16 + (g >> 1)*8 + l7;
      int ch  = 2*ks + (g & 1);
      ldm4(bfr[ntp*2][0], bfr[ntp*2][1], bfr[ntp*2+1][0], bfr[ntp*2+1][1],
           baseB + (sw_idx(row, ch) << 4));
    }
    #pragma unroll
    for (int mt = 0; mt < 2; mt++)
      #pragma unroll
      for (int nt = 0; nt < 8; nt++)
        mma_fp8(acc[mt][nt], afr[mt], bfr[nt]);
  }
}

// ---------------------------------------------------------------------------
// K0a: weights fp32 -> e4m3 with scaling + alpha
// ---------------------------------------------------------------------------
__global__ void k_convert(const float* __restrict__ W1, const float* __restrict__ W2,
                          const float* __restrict__ alpha_raw){
  int t = blockIdx.x*blockDim.x + threadIdx.x;
  if (t == 0) g_alpha = log1pf(expf(alpha_raw[0]));
  if (t < HID*KDIM/4){
    float4 a = ((const float4*)W1)[t];
    float4 b = ((const float4*)W2)[t];
    ((uint32_t*)g_W18)[t] = fp8x4(16.f*a.x, 16.f*a.y, 16.f*a.z, 16.f*a.w);
    ((uint32_t*)g_W28)[t] = fp8x4(1024.f*b.x, 1024.f*b.y, 1024.f*b.z, 1024.f*b.w);
  }
}

// K0b: x fp32 -> e4m3
__global__ void k_convx(const float* __restrict__ x){
  size_t t = (size_t)blockIdx.x*blockDim.x + threadIdx.x;
  if (t < TOT/4){
    float4 a = ((const float4*)x)[t];
    ((uint32_t*)g_x8)[t] = fp8x4(a.x, a.y, a.z, a.w);
  }
}

// ---------------------------------------------------------------------------
// K1: FP8 GEMM1 (implicit im2col) + bias + exact GELU -> G e4m3 [M_PAD, 256]
//     block 64(M) x 256(N), K=4096 in 64 slabs of 64
// ---------------------------------------------------------------------------
__global__ void __launch_bounds__(256, 2) k_gemm1(const float* __restrict__ b1){
  __shared__ uint4 sA[2][256];    // 64 rows x 64B
  __shared__ uint4 sB[2][1024];   // 256 rows x 64B
  const int tid  = threadIdx.x;
  const int lane = tid & 31, warp = tid >> 5;
  const int wm = warp & 1, wn = warp >> 1;
  const int l0 = blockIdx.x * 64;

  // A loader: thread -> row r=tid>>2 (patch), chunk c2=tid&3 (kh pair 2c2,2c2+1)
  const int rA = tid >> 2, c2 = tid & 3;
  const int l = l0 + rA;
  const bool av = (l < M_TOT);
  int bb = 0, ph = 0, pw = 0;
  if (av){ bb = l / LPB; int rem = l - bb*LPB; ph = rem / NW; pw = rem - ph*NW; }
  const uint8_t* abase = g_x8 + (size_t)bb*4194304 + (size_t)(ph*4 + 2*c2)*256 + pw*4;
  // B loader: thread -> W1 row n=tid, all 4 chunks
  const uint8_t* bbase = g_W18 + (size_t)tid*KDIM;
  const int aidx = sw_idx(rA, c2);

  float acc[2][8][4];
  #pragma unroll
  for (int a = 0; a < 2; a++)
    #pragma unroll
    for (int b = 0; b < 8; b++)
      #pragma unroll
      for (int c = 0; c < 4; c++) acc[a][b][c] = 0.f;

  uint32_t u0, u1, u2, u3; uint4 bv[4];

  // prologue: slab 0 (channel 0)
  {
    u0 = u1 = u2 = u3 = 0;
    if (av){
      u0 = *(const uint32_t*)(abase);
      u1 = *(const uint32_t*)(abase + 4);
      u2 = *(const uint32_t*)(abase + 256);
      u3 = *(const uint32_t*)(abase + 260);
    }
    #pragma unroll
    for (int c = 0; c < 4; c++) bv[c] = *(const uint4*)(bbase + c*16);
    sA[0][aidx] = make_uint4(u0, u1, u2, u3);
    #pragma unroll
    for (int c = 0; c < 4; c++) sB[0][sw_idx(tid, c)] = bv[c];
  }
  __syncthreads();

  const int NS = KDIM / 64;  // 64 slabs (slab s = channel s)
  for (int s = 0; s < NS; s++){
    int st = s & 1;
    bool more = (s + 1) < NS;
    if (more){
      const uint8_t* ap = abase + (size_t)(s+1)*65536;
      u0 = u1 = u2 = u3 = 0;
      if (av){
        u0 = *(const uint32_t*)(ap);
        u1 = *(const uint32_t*)(ap + 4);
        u2 = *(const uint32_t*)(ap + 256);
        u3 = *(const uint32_t*)(ap + 260);
      }
      #pragma unroll
      for (int c = 0; c < 4; c++) bv[c] = *(const uint4*)(bbase + (s+1)*64 + c*16);
    }
    compute_tile(sA[st], sB[st], wm, wn, lane, acc);
    if (more){
      sA[st^1][aidx] = make_uint4(u0, u1, u2, u3);
      #pragma unroll
      for (int c = 0; c < 4; c++) sB[st^1][sw_idx(tid, c)] = bv[c];
    }
    __syncthreads();
  }

  // epilogue: descale + bias + exact GELU -> e4m3 (padded rows too: deterministic)
  #pragma unroll
  for (int mt = 0; mt < 2; mt++){
    #pragma unroll
    for (int hf = 0; hf < 2; hf++){
      int r = wm*32 + mt*16 + (lane >> 2) + hf*8;
      size_t ll = (size_t)l0 + r;
      uint8_t* gp = g_G8 + ll*HID;
      #pragma unroll
      for (int nt = 0; nt < 8; nt++){
        int n = wn*64 + nt*8 + (lane & 3)*2;
        float v0 = acc[mt][nt][hf*2+0]*SC1 + b1[n];
        float v1 = acc[mt][nt][hf*2+1]*SC1 + b1[n+1];
        v0 = 0.5f*v0*(1.f + erff(v0*0.70710678118654752f));
        v1 = 0.5f*v1*(1.f + erff(v1*0.70710678118654752f));
        *(unsigned short*)(gp + n) = fp8x2(v0, v1);
      }
    }
  }
}

// ---------------------------------------------------------------------------
// K2: FP8 GEMM2 -> descale + bias, scatter to 4 phase images
//     block 64(M) x 256(N of 4096), K=256 in 4 slabs of 64
// ---------------------------------------------------------------------------
__global__ void __launch_bounds__(256, 2) k_gemm2(const float* __restrict__ b2){
  __shared__ uint4 sA[2][256];
  __shared__ uint4 sB[2][1024];
  const int tid  = threadIdx.x;
  const int lane = tid & 31, warp = tid >> 5;
  const int wm = warp & 1, wn = warp >> 1;
  const int l0 = blockIdx.y * 64;
  const int n0 = blockIdx.x * 256;

  const int rA = tid >> 2, c2 = tid & 3;
  const uint8_t* abase = g_G8 + (size_t)(l0 + rA)*HID + c2*16;   // row < 16000 always
  const uint8_t* bbase = g_W28 + (size_t)(n0 + tid)*HID;
  const int aidx = sw_idx(rA, c2);

  float acc[2][8][4];
  #pragma unroll
  for (int a = 0; a < 2; a++)
    #pragma unroll
    for (int b = 0; b < 8; b++)
      #pragma unroll
      for (int c = 0; c < 4; c++) acc[a][b][c] = 0.f;

  uint4 fa; uint4 bv[4];

  // prologue slab 0
  fa = *(const uint4*)(abase);
  #pragma unroll
  for (int c = 0; c < 4; c++) bv[c] = *(const uint4*)(bbase + c*16);
  sA[0][aidx] = fa;
  #pragma unroll
  for (int c = 0; c < 4; c++) sB[0][sw_idx(tid, c)] = bv[c];
  __syncthreads();

  const int NS = HID / 64;  // 4
  for (int s = 0; s < NS; s++){
    int st = s & 1;
    bool more = (s + 1) < NS;
    if (more){
      fa = *(const uint4*)(abase + (s+1)*64);
      #pragma unroll
      for (int c = 0; c < 4; c++) bv[c] = *(const uint4*)(bbase + (s+1)*64 + c*16);
    }
    compute_tile(sA[st], sB[st], wm, wn, lane, acc);
    if (more){
      sA[st^1][aidx] = fa;
      #pragma unroll
      for (int c = 0; c < 4; c++) sB[st^1][sw_idx(tid, c)] = bv[c];
    }
    __syncthreads();
  }

  // epilogue: descale + bias, scatter bf16x2 pairs into phase images
  #pragma unroll
  for (int mt = 0; mt < 2; mt++){
    #pragma unroll
    for (int hf = 0; hf < 2; hf++){
      int r = wm*32 + mt*16 + (lane >> 2) + hf*8;
      int l = l0 + r;
      if (l >= M_TOT) continue;
      int bb = l / LPB; int rem = l - bb*LPB;
      int ph = rem / NW; int pw = rem - ph*NW;
      #pragma unroll
      for (int nt = 0; nt < 8; nt++){
        int n  = n0 + wn*64 + nt*8 + (lane & 3)*2;
        int c  = n >> 6, kh = (n >> 3) & 7, kw = n & 7;  // kw pair shares phase
        int dlt = ((kh >> 2) << 1) | (kw >> 2);
        int i = ph*4 + kh;
        int j = pw*4 + kw;
        float v0 = acc[mt][nt][hf*2+0]*SC2 + b2[n];
        float v1 = acc[mt][nt][hf*2+1]*SC2 + b2[n+1];
        size_t idx = (((size_t)(dlt*NB + bb)*NC + c) << 16) + ((size_t)i << 8) + j;
        *(__nv_bfloat162*)(g_img + idx) = __floats2bfloat162_rn(v0, v1);
      }
    }
  }
}

// ---------------------------------------------------------------------------
// K3: blend  out = x + alpha * (sum of valid phase images)/norm  (x4 vectorized)
// ---------------------------------------------------------------------------
__global__ void k_blend(const float* __restrict__ x, float* __restrict__ out){
  size_t t = (size_t)blockIdx.x*blockDim.x + threadIdx.x;
  if (t >= TOT/4) return;
  size_t e = t*4;
  int j0 = (int)(e & 255);
  int i  = (int)((e >> 8) & 255);
  bool h0 = (i <= 251), h1 = (i >= 4), w0 = (j0 < 252), w1 = (j0 >= 4);

  float4 xv = *(const float4*)(x + e);
  float s0 = 0.f, s1 = 0.f, s2 = 0.f, s3 = 0.f;
  #pragma unroll
  for (int d = 0; d < 4; d++){
    bool v = (d == 0) ? (h0 && w0) : (d == 1) ? (h0 && w1) : (d == 2) ? (h1 && w0) : (h1 && w1);
    if (v){
      uint2 p = *(const uint2*)(g_img + (size_t)d*TOT + e);
      float2 f0 = __bfloat1622float2(*(const __nv_bfloat162*)&p.x);
      float2 f1 = __bfloat1622float2(*(const __nv_bfloat162*)&p.y);
      s0 += f0.x; s1 += f0.y; s2 += f1.x; s3 += f1.y;
    }
  }
  float scale = g_alpha * (((h0 && h1) ? 0.5f : 1.0f) * ((w0 && w1) ? 0.5f : 1.0f));
  float4 ov;
  ov.x = xv.x + scale * s0;
  ov.y = xv.y + scale * s1;
  ov.z = xv.z + scale * s2;
  ov.w = xv.w + scale * s3;
  *(float4*)(out + e) = ov;
}

// ---------------------------------------------------------------------------
extern "C" void kernel_launch(void* const* d_in, const int* in_sizes, int n_in,
                              void* d_out, int out_size){
  (void)in_sizes; (void)n_in; (void)out_size;
  const float* x         = (const float*)d_in[0];
  const float* W1        = (const float*)d_in[1];
  const float* b1        = (const float*)d_in[2];
  const float* W2        = (const float*)d_in[3];
  const float* b2        = (const float*)d_in[4];
  const float* alpha_raw = (const float*)d_in[5];
  float* out = (float*)d_out;

  k_convert<<<(HID*KDIM/4 + 255)/256, 256>>>(W1, W2, alpha_raw);
  k_convx<<<(int)((TOT/4 + 255)/256), 256>>>(x);
  k_gemm1<<<250, 256>>>(b1);
  k_gemm2<<<dim3(16, 250), 256>>>(b2);
  k_blend<<<(int)((TOT/4 + 255)/256), 256>>>(x, out);
}

// round 11
// speedup vs baseline: 1.3318x; 1.3318x over previous
#include <cuda_runtime.h>
#include <cuda_bf16.h>
#include <cstdint>

// Problem constants
#define NB 4
#define NC 64
#define NHH 256
#define NWW 256
#define NH 63
#define NW 63
#define LPB (NH*NW)        // 3969
#define M_TOT (NB*LPB)     // 15876
#define M_PAD 16000
#define KDIM 4096
#define HID 256
#define TOT ((size_t)NB*NC*NHH*NWW)   // 16777216

// Scratch (static device globals)
static __device__ __nv_bfloat16 g_W1b[(size_t)HID*KDIM];     // 2 MB
static __device__ __nv_bfloat16 g_W2b[(size_t)KDIM*HID];     // 2 MB
static __device__ __nv_bfloat16 g_xb[(size_t)TOT];           // 32 MB
static __device__ __nv_bfloat16 g_G[(size_t)M_PAD*HID];      // 8 MB
static __device__ __nv_bfloat16 g_img[(size_t)4*TOT];        // 134 MB
static __device__ float g_alpha;

// ---------------------------------------------------------------------------
// mma / cp.async helpers
// ---------------------------------------------------------------------------
__device__ __forceinline__ void ldm4(uint32_t& r0, uint32_t& r1, uint32_t& r2, uint32_t& r3, uint32_t a){
  asm volatile("ldmatrix.sync.aligned.m8n8.x4.shared.b16 {%0,%1,%2,%3},[%4];\n"
    : "=r"(r0), "=r"(r1), "=r"(r2), "=r"(r3) : "r"(a));
}
__device__ __forceinline__ void mma_bf16(float* d, const uint32_t* a, const uint32_t* b){
  asm volatile("mma.sync.aligned.m16n8k16.row.col.f32.bf16.bf16.f32 "
    "{%0,%1,%2,%3},{%4,%5,%6,%7},{%8,%9},{%0,%1,%2,%3};\n"
    : "+f"(d[0]), "+f"(d[1]), "+f"(d[2]), "+f"(d[3])
    : "r"(a[0]), "r"(a[1]), "r"(a[2]), "r"(a[3]), "r"(b[0]), "r"(b[1]));
}
// 16B cp.async (requires 16B-aligned src)
__device__ __forceinline__ void cpa16(uint32_t dst, const void* src, uint32_t sz){
  asm volatile("cp.async.cg.shared.global [%0], [%1], 16, %2;\n"
    :: "r"(dst), "l"(src), "r"(sz) : "memory");
}
// 8B cp.async (requires only 8B-aligned src) — for the im2col A path (pw*8 B offsets)
__device__ __forceinline__ void cpa8(uint32_t dst, const void* src, uint32_t sz){
  asm volatile("cp.async.ca.shared.global [%0], [%1], 8, %2;\n"
    :: "r"(dst), "l"(src), "r"(sz) : "memory");
}
#define CP_COMMIT() asm volatile("cp.async.commit_group;\n" ::: "memory")
#define CP_WAIT2()  asm volatile("cp.async.wait_group 2;\n" ::: "memory")
#define CP_WAIT0()  asm volatile("cp.async.wait_group 0;\n" ::: "memory")

// smem tile: rows x 4 chunks of 16B (BK=32 bf16). XOR swizzle: conflict-free ldmatrix.
__device__ __forceinline__ int sw_idx(int row, int ch){ return row*4 + (ch ^ ((row>>1)&3)); }

// Pipeline geometry: stage = [A: 64 rows x 64B = 4KB][B: 256 rows x 64B = 16KB]
#define STG 20480
#define NST 4
#define DSM (STG*NST)   // 80 KB dynamic smem; 2 CTAs/SM = 160 KB

// One BK=32 slab per warp: 2 k16 steps, warp tile 32(M) x 64(N).
// Block tile: BM=64 (wm in {0,1}), BN=256 (wn in {0..3}).
__device__ __forceinline__ void compute_tile(uint32_t baseA, uint32_t baseB,
                                             int wm, int wn, int lane, float (*acc)[8][4]){
  #pragma unroll
  for (int ks = 0; ks < 2; ks++){
    uint32_t afr[2][4], bfr[8][2];
    #pragma unroll
    for (int mt = 0; mt < 2; mt++){
      int row = wm*32 + mt*16 + (lane & 15);
      int ch  = ks*2 + (lane >> 4);
      ldm4(afr[mt][0], afr[mt][1], afr[mt][2], afr[mt][3], baseA + (sw_idx(row, ch) << 4));
    }
    #pragma unroll
    for (int ntp = 0; ntp < 4; ntp++){
      int g   = lane >> 3;
      int row = wn*64 + ntp*16 + (g >> 1)*8 + (lane & 7);
      int ch  = ks*2 + (g & 1);
      ldm4(bfr[ntp*2][0], bfr[ntp*2][1], bfr[ntp*2+1][0], bfr[ntp*2+1][1],
           baseB + (sw_idx(row, ch) << 4));
    }
    #pragma unroll
    for (int mt = 0; mt < 2; mt++)
      #pragma unroll
      for (int nt = 0; nt < 8; nt++)
        mma_bf16(acc[mt][nt], afr[mt], bfr[nt]);
  }
}

// ---------------------------------------------------------------------------
// K0a: weights fp32 -> bf16 + alpha
// ---------------------------------------------------------------------------
__global__ void k_convert(const float* __restrict__ W1, const float* __restrict__ W2,
                          const float* __restrict__ alpha_raw){
  int t = blockIdx.x*blockDim.x + threadIdx.x;
  if (t == 0) g_alpha = log1pf(expf(alpha_raw[0]));
  if (t < HID*KDIM/4){
    float4 a = ((const float4*)W1)[t];
    float4 b = ((const float4*)W2)[t];
    uint2 pa, pb;
    *(__nv_bfloat162*)&pa.x = __floats2bfloat162_rn(a.x, a.y);
    *(__nv_bfloat162*)&pa.y = __floats2bfloat162_rn(a.z, a.w);
    *(__nv_bfloat162*)&pb.x = __floats2bfloat162_rn(b.x, b.y);
    *(__nv_bfloat162*)&pb.y = __floats2bfloat162_rn(b.z, b.w);
    ((uint2*)g_W1b)[t] = pa;
    ((uint2*)g_W2b)[t] = pb;
  }
}

// K0b: x fp32 -> bf16
__global__ void k_convx(const float* __restrict__ x){
  size_t t = (size_t)blockIdx.x*blockDim.x + threadIdx.x;
  if (t < TOT/4){
    float4 a = ((const float4*)x)[t];
    uint2 p;
    *(__nv_bfloat162*)&p.x = __floats2bfloat162_rn(a.x, a.y);
    *(__nv_bfloat162*)&p.y = __floats2bfloat162_rn(a.z, a.w);
    ((uint2*)g_xb)[t] = p;
  }
}

// ---------------------------------------------------------------------------
// K1: GEMM1 (implicit im2col, cp.async 4-stage) + bias + GELU -> G bf16
//     block 64(M) x 256(N), K=4096 in 128 slabs of 32
// ---------------------------------------------------------------------------
__global__ void __launch_bounds__(256, 2) k_gemm1(const float* __restrict__ b1){
  extern __shared__ char dsm[];
  const uint32_t sbase = (uint32_t)__cvta_generic_to_shared(dsm);
  const int tid  = threadIdx.x;
  const int lane = tid & 31, warp = tid >> 5;
  const int wm = warp & 1, wn = warp >> 1;
  const int l0 = blockIdx.x * 64;

  const int rr = tid >> 2, ch = tid & 3;
  const int l = l0 + rr;
  const bool av = (l < M_TOT);
  const uint32_t asz = av ? 8u : 0u;
  int bb = 0, ph = 0, pw = 0;
  if (av){ bb = l / LPB; int rem = l - bb*LPB; ph = rem / NW; pw = rem - ph*NW; }
  const __nv_bfloat16* xb = g_xb + (size_t)bb*(NC*65536) + (size_t)(ph*4)*256 + pw*4;
  const __nv_bfloat16* wp[4];
  #pragma unroll
  for (int q = 0; q < 4; q++) wp[q] = g_W1b + (size_t)(rr + 64*q)*KDIM + ch*8;
  const uint32_t adst = (uint32_t)(sw_idx(rr, ch) << 4);
  uint32_t bdst[4];
  #pragma unroll
  for (int q = 0; q < 4; q++) bdst[q] = 4096u + (uint32_t)(sw_idx(rr + 64*q, ch) << 4);

  const int KT = KDIM / 32;  // 128
  // prologue: stages 0..2
  #pragma unroll
  for (int kt = 0; kt < 3; kt++){
    uint32_t sb = sbase + (uint32_t)kt*STG;
    int k = kt*32 + ch*8;
    const __nv_bfloat16* asrc = xb + (k >> 6)*65536 + ((k >> 3) & 7)*256;
    cpa8(sb + adst,      asrc,     asz);   // 8B-aligned src (pw*8 B)
    cpa8(sb + adst + 8u, asrc + 4, asz);
    #pragma unroll
    for (int q = 0; q < 4; q++) cpa16(sb + bdst[q], wp[q] + kt*32, 16u);
    CP_COMMIT();
  }

  float acc[2][8][4];
  #pragma unroll
  for (int a = 0; a < 2; a++)
    #pragma unroll
    for (int b = 0; b < 8; b++)
      #pragma unroll
      for (int c = 0; c < 4; c++) acc[a][b][c] = 0.f;

  for (int kt = 0; kt < KT; kt++){
    if (kt + 2 < KT) CP_WAIT2(); else CP_WAIT0();
    __syncthreads();
    uint32_t sb = sbase + (uint32_t)(kt & 3)*STG;
    compute_tile(sb, sb + 4096u, wm, wn, lane, acc);
    int kn = kt + 3;
    if (kn < KT){
      uint32_t sn = sbase + (uint32_t)(kn & 3)*STG;
      int k = kn*32 + ch*8;
      const __nv_bfloat16* asrc = xb + (k >> 6)*65536 + ((k >> 3) & 7)*256;
      cpa8(sn + adst,      asrc,     asz);
      cpa8(sn + adst + 8u, asrc + 4, asz);
      #pragma unroll
      for (int q = 0; q < 4; q++) cpa16(sn + bdst[q], wp[q] + kn*32, 16u);
      CP_COMMIT();
    }
  }

  // epilogue: bias + exact GELU -> G bf16 (padded rows written too: deterministic)
  #pragma unroll
  for (int mt = 0; mt < 2; mt++){
    #pragma unroll
    for (int hf = 0; hf < 2; hf++){
      int r = wm*32 + mt*16 + (lane >> 2) + hf*8;
      size_t ll = (size_t)l0 + r;
      __nv_bfloat16* gp = g_G + ll*HID;
      #pragma unroll
      for (int nt = 0; nt < 8; nt++){
        int n = wn*64 + nt*8 + (lane & 3)*2;
        float v0 = acc[mt][nt][hf*2+0] + b1[n];
        float v1 = acc[mt][nt][hf*2+1] + b1[n+1];
        v0 = 0.5f*v0*(1.f + erff(v0*0.70710678118654752f));
        v1 = 0.5f*v1*(1.f + erff(v1*0.70710678118654752f));
        *(__nv_bfloat162*)(gp + n) = __floats2bfloat162_rn(v0, v1);
      }
    }
  }
}

// ---------------------------------------------------------------------------
// K2: GEMM2 (cp.async 4-stage) -> bias, scatter to 4 phase images
//     block 64(M) x 256(N of 4096), K=256 in 8 slabs of 32
// ---------------------------------------------------------------------------
__global__ void __launch_bounds__(256, 2) k_gemm2(const float* __restrict__ b2){
  extern __shared__ char dsm[];
  const uint32_t sbase = (uint32_t)__cvta_generic_to_shared(dsm);
  const int tid  = threadIdx.x;
  const int lane = tid & 31, warp = tid >> 5;
  const int wm = warp & 1, wn = warp >> 1;
  const int l0 = blockIdx.y * 64;
  const int n0 = blockIdx.x * 256;

  const int rr = tid >> 2, ch = tid & 3;
  const __nv_bfloat16* ga = g_G + (size_t)(l0 + rr)*HID + ch*8;   // rows < 16000 always valid
  const __nv_bfloat16* wp[4];
  #pragma unroll
  for (int q = 0; q < 4; q++) wp[q] = g_W2b + (size_t)(n0 + rr + 64*q)*HID + ch*8;
  const uint32_t adst = (uint32_t)(sw_idx(rr, ch) << 4);
  uint32_t bdst[4];
  #pragma unroll
  for (int q = 0; q < 4; q++) bdst[q] = 4096u + (uint32_t)(sw_idx(rr + 64*q, ch) << 4);

  const int KT = HID / 32;  // 8
  #pragma unroll
  for (int kt = 0; kt < 3; kt++){
    uint32_t sb = sbase + (uint32_t)kt*STG;
    cpa16(sb + adst, ga + kt*32, 16u);
    #pragma unroll
    for (int q = 0; q < 4; q++) cpa16(sb + bdst[q], wp[q] + kt*32, 16u);
    CP_COMMIT();
  }

  float acc[2][8][4];
  #pragma unroll
  for (int a = 0; a < 2; a++)
    #pragma unroll
    for (int b = 0; b < 8; b++)
      #pragma unroll
      for (int c = 0; c < 4; c++) acc[a][b][c] = 0.f;

  for (int kt = 0; kt < KT; kt++){
    if (kt + 2 < KT) CP_WAIT2(); else CP_WAIT0();
    __syncthreads();
    uint32_t sb = sbase + (uint32_t)(kt & 3)*STG;
    compute_tile(sb, sb + 4096u, wm, wn, lane, acc);
    int kn = kt + 3;
    if (kn < KT){
      uint32_t sn = sbase + (uint32_t)(kn & 3)*STG;
      cpa16(sn + adst, ga + kn*32, 16u);
      #pragma unroll
      for (int q = 0; q < 4; q++) cpa16(sn + bdst[q], wp[q] + kn*32, 16u);
      CP_COMMIT();
    }
  }

  // epilogue: bias, scatter bf16x2 pairs into phase images
  #pragma unroll
  for (int mt = 0; mt < 2; mt++){
    #pragma unroll
    for (int hf = 0; hf < 2; hf++){
      int r = wm*32 + mt*16 + (lane >> 2) + hf*8;
      int l = l0 + r;
      if (l >= M_TOT) continue;
      int bb = l / LPB; int rem = l - bb*LPB;
      int ph = rem / NW; int pw = rem - ph*NW;
      #pragma unroll
      for (int nt = 0; nt < 8; nt++){
        int n  = n0 + wn*64 + nt*8 + (lane & 3)*2;
        int c  = n >> 6, kh = (n >> 3) & 7, kw = n & 7;  // kw pair shares phase
        int dlt = ((kh >> 2) << 1) | (kw >> 2);
        int i = ph*4 + kh;
        int j = pw*4 + kw;
        float v0 = acc[mt][nt][hf*2+0] + b2[n];
        float v1 = acc[mt][nt][hf*2+1] + b2[n+1];
        size_t idx = (((size_t)(dlt*NB + bb)*NC + c) << 16) + ((size_t)i << 8) + j;
        *(__nv_bfloat162*)(g_img + idx) = __floats2bfloat162_rn(v0, v1);
      }
    }
  }
}

// ---------------------------------------------------------------------------
// K3: blend  out = x + alpha * (sum of valid phase images)/norm  (x4 vectorized)
// ---------------------------------------------------------------------------
__global__ void k_blend(const float* __restrict__ x, float* __restrict__ out){
  size_t t = (size_t)blockIdx.x*blockDim.x + threadIdx.x;
  if (t >= TOT/4) return;
  size_t e = t*4;
  int j0 = (int)(e & 255);
  int i  = (int)((e >> 8) & 255);
  bool h0 = (i <= 251), h1 = (i >= 4), w0 = (j0 < 252), w1 = (j0 >= 4);

  float4 xv = *(const float4*)(x + e);
  float s0 = 0.f, s1 = 0.f, s2 = 0.f, s3 = 0.f;
  #pragma unroll
  for (int d = 0; d < 4; d++){
    bool v = (d == 0) ? (h0 && w0) : (d == 1) ? (h0 && w1) : (d == 2) ? (h1 && w0) : (h1 && w1);
    if (v){
      uint2 p = *(const uint2*)(g_img + (size_t)d*TOT + e);
      float2 f0 = __bfloat1622float2(*(const __nv_bfloat162*)&p.x);
      float2 f1 = __bfloat1622float2(*(const __nv_bfloat162*)&p.y);
      s0 += f0.x; s1 += f0.y; s2 += f1.x; s3 += f1.y;
    }
  }
  float scale = g_alpha * (((h0 && h1) ? 0.5f : 1.0f) * ((w0 && w1) ? 0.5f : 1.0f));
  float4 ov;
  ov.x = xv.x + scale * s0;
  ov.y = xv.y + scale * s1;
  ov.z = xv.z + scale * s2;
  ov.w = xv.w + scale * s3;
  *(float4*)(out + e) = ov;
}

// ---------------------------------------------------------------------------
extern "C" void kernel_launch(void* const* d_in, const int* in_sizes, int n_in,
                              void* d_out, int out_size){
  (void)in_sizes; (void)n_in; (void)out_size;
  const float* x         = (const float*)d_in[0];
  const float* W1        = (const float*)d_in[1];
  const float* b1        = (const float*)d_in[2];
  const float* W2        = (const float*)d_in[3];
  const float* b2        = (const float*)d_in[4];
  const float* alpha_raw = (const float*)d_in[5];
  float* out = (float*)d_out;

  // host-side attribute set (not an allocation; unconditional & deterministic)
  cudaFuncSetAttribute(k_gemm1, cudaFuncAttributeMaxDynamicSharedMemorySize, DSM);
  cudaFuncSetAttribute(k_gemm2, cudaFuncAttributeMaxDynamicSharedMemorySize, DSM);

  k_convert<<<(HID*KDIM/4 + 255)/256, 256>>>(W1, W2, alpha_raw);
  k_convx<<<(int)((TOT/4 + 255)/256), 256>>>(x);
  k_gemm1<<<250, 256, DSM>>>(b1);
  k_gemm2<<<dim3(16, 250), 256, DSM>>>(b2);
  k_blend<<<(int)((TOT/4 + 255)/256), 256>>>(x, out);
}